// round 6
// baseline (speedup 1.0000x reference)
#include <cuda_runtime.h>
#include <cuda_bf16.h>

#define HH 512
#define WW 512
#define HWN (HH * WW)           // 262144 = 1<<18
#define NB 8
#define NC 16

// Scratch: scatter-winner per target pixel (largest source pixel index wins,
// matching sequential last-write-wins of the reference scatter).
__device__ int   g_winner[NB * HWN];
__device__ float g_M[NB][9];

// ---------------------------------------------------------------------------
// M[b] = (K @ R[b]) @ Kinv  (association A; best fingerprint so far).
// Each dot: k-ascending FMA accumulation from zero (gemm semantics).
// ---------------------------------------------------------------------------
__global__ void compute_M_kernel(const float* __restrict__ R,
                                 const float* __restrict__ K,
                                 const float* __restrict__ Kinv) {
    int b = threadIdx.x;
    if (b >= NB) return;
    const float* Rb = R + b * 9;
    float KR[9];
#pragma unroll
    for (int i = 0; i < 3; i++) {
#pragma unroll
        for (int k = 0; k < 3; k++) {
            float s = __fmul_rn(K[i * 3 + 0], Rb[0 * 3 + k]);
            s = __fmaf_rn(K[i * 3 + 1], Rb[1 * 3 + k], s);
            s = __fmaf_rn(K[i * 3 + 2], Rb[2 * 3 + k], s);
            KR[i * 3 + k] = s;
        }
    }
#pragma unroll
    for (int i = 0; i < 3; i++) {
#pragma unroll
        for (int j = 0; j < 3; j++) {
            float s = __fmul_rn(KR[i * 3 + 0], Kinv[0 * 3 + j]);
            s = __fmaf_rn(KR[i * 3 + 1], Kinv[1 * 3 + j], s);
            s = __fmaf_rn(KR[i * 3 + 2], Kinv[2 * 3 + j], s);
            g_M[b][i * 3 + j] = s;
        }
    }
}

// ---------------------------------------------------------------------------
// Winner init: -1 everywhere (vectorized int4 stores)
// ---------------------------------------------------------------------------
__global__ void init_winner_kernel() {
    int i = blockIdx.x * blockDim.x + threadIdx.x;
    ((int4*)g_winner)[i] = make_int4(-1, -1, -1, -1);
}

// ---------------------------------------------------------------------------
// Projection + scatter: one thread per (b, pixel p).
// XLA algebraic-simplifier semantics: divide-by-broadcast is rewritten to
// multiply-by-reciprocal:
//   T/d          -> T * (1/d)
//   t / t[:,2:]  -> t * (1/t2)
// with the reciprocal correctly rounded (__frcp_rn) and the multiply a
// separate rounding (__fmul_rn). x-chain: gemm FMA accumulation. t = x + y
// one add.
// ---------------------------------------------------------------------------
__global__ void scatter_kernel(const float* __restrict__ depth,
                               const float* __restrict__ T,
                               const float* __restrict__ K) {
    int idx = blockIdx.x * blockDim.x + threadIdx.x;   // 0 .. NB*HWN-1
    int b = idx >> 18;
    int p = idx & (HWN - 1);
    float gx = (float)(p >> 9);
    float gy = (float)(p & 511);

    float d = fmaxf(depth[idx], 0.1f);

    // T/d  ->  T * (1/d)   (reciprocal hoisted to the small shape)
    float rd = __frcp_rn(d);
    float v0 = __fmul_rn(T[b * 3 + 0], rd);
    float v1 = __fmul_rn(T[b * 3 + 1], rd);
    float v2 = __fmul_rn(T[b * 3 + 2], rd);

    const float* M = g_M[b];
    // x_i = fadd(fma(M_i1, gy, fmul(M_i0, gx)), M_i2)   (gemm k-chain)
    float x0 = __fadd_rn(__fmaf_rn(M[1], gy, __fmul_rn(M[0], gx)), M[2]);
    float x1 = __fadd_rn(__fmaf_rn(M[4], gy, __fmul_rn(M[3], gx)), M[5]);
    float x2 = __fadd_rn(__fmaf_rn(M[7], gy, __fmul_rn(M[6], gx)), M[8]);

    // y_i = fma(K_i2, v2, fma(K_i1, v1, fmul(K_i0, v0)))  (form-invariant)
    float y0 = __fmaf_rn(K[2], v2, __fmaf_rn(K[1], v1, __fmul_rn(K[0], v0)));
    float y1 = __fmaf_rn(K[5], v2, __fmaf_rn(K[4], v1, __fmul_rn(K[3], v0)));
    float y2 = __fmaf_rn(K[8], v2, __fmaf_rn(K[7], v1, __fmul_rn(K[6], v0)));

    float t0 = __fadd_rn(x0, y0);
    float t1 = __fadd_rn(x1, y1);
    float t2 = __fadd_rn(x2, y2);

    if (t0 == 0.0f) t0 = 1e-4f;
    if (t1 == 0.0f) t1 = 1e-4f;
    if (t2 == 0.0f) t2 = 1e-4f;

    // t / t2  ->  t * (1/t2)
    float rt2 = __frcp_rn(t2);
    float u = __fmul_rn(t0, rt2);
    float v = __fmul_rn(t1, rt2);
    u = fminf(fmaxf(u, 0.0f), 511.0f);
    v = fminf(fmaxf(v, 0.0f), 511.0f);

    int q = ((int)u << 9) + (int)v;
    atomicMax(&g_winner[(b << 18) + q], p);
}

// ---------------------------------------------------------------------------
// Gather + maxpool(2x2) + nearest upsample(x2), fused.
// Block = 256 threads covering a pooled tile of 4 rows x 64 cols.
// Winners for the tile (8 src rows x 128 src cols) staged in smem and
// shared across all 16 channels.
// ---------------------------------------------------------------------------
__global__ void gather_pool_kernel(const float* __restrict__ image,
                                   float* __restrict__ out) {
    int tile = blockIdx.x & 255;   // 256 tiles per image (64 i-tiles x 4 j-tiles)
    int b    = blockIdx.x >> 8;
    int i0 = (tile >> 2) * 4;      // pooled-row start (0..252)
    int j0 = (tile & 3) * 64;      // pooled-col start (0..192)

    __shared__ int sw[8][128];

    int tid = threadIdx.x;
    const int* wbase = g_winner + (b << 18) + (2 * i0) * WW + 2 * j0;
#pragma unroll
    for (int k = 0; k < 4; k++) {
        int lin = tid + k * 256;          // 0..1023
        int r = lin >> 7, c = lin & 127;
        sw[r][c] = wbase[r * WW + c];
    }
    __syncthreads();

    int li = tid >> 6;                    // 0..3  pooled row within tile
    int jj = tid & 63;                    // 0..63 pooled col within tile
    int w00 = sw[2 * li][2 * jj];
    int w01 = sw[2 * li][2 * jj + 1];
    int w10 = sw[2 * li + 1][2 * jj];
    int w11 = sw[2 * li + 1][2 * jj + 1];

    int i2 = i0 + li;
    int j2 = j0 + jj;
    int opix = (2 * i2) * WW + 2 * j2;

#pragma unroll
    for (int c = 0; c < NC; c++) {
        const float* img = image + ((unsigned)(b * NC + c) << 18);
        float a0 = 0.0f, a1 = 0.0f, a2 = 0.0f, a3 = 0.0f;
        if (w00 >= 0) a0 = __ldg(img + w00);
        if (w01 >= 0) a1 = __ldg(img + w01);
        if (w10 >= 0) a2 = __ldg(img + w10);
        if (w11 >= 0) a3 = __ldg(img + w11);
        float m = fmaxf(fmaxf(a0, a1), fmaxf(a2, a3));

        float* o = out + ((unsigned)(b * NC + c) << 18) + opix;
        float2 vv = make_float2(m, m);
        *(float2*)(o)      = vv;
        *(float2*)(o + WW) = vv;
    }
}

// ---------------------------------------------------------------------------
extern "C" void kernel_launch(void* const* d_in, const int* in_sizes, int n_in,
                              void* d_out, int out_size) {
    const float* image = (const float*)d_in[0];   // [8,16,512,512]
    const float* depth = (const float*)d_in[1];   // [8,512,512]
    const float* T     = (const float*)d_in[2];   // [8,3,1]
    const float* R     = (const float*)d_in[3];   // [8,3,3]
    const float* K     = (const float*)d_in[4];   // [3,3]
    const float* Kinv  = (const float*)d_in[5];   // [3,3]
    float* out = (float*)d_out;

    compute_M_kernel<<<1, 32>>>(R, K, Kinv);
    init_winner_kernel<<<(NB * HWN / 4) / 256, 256>>>();
    scatter_kernel<<<(NB * HWN) / 256, 256>>>(depth, T, K);
    gather_pool_kernel<<<NB * 256, 256>>>(image, out);
}

// round 7
// speedup vs baseline: 1.0357x; 1.0357x over previous
#include <cuda_runtime.h>
#include <cuda_bf16.h>

#define HH 512
#define WW 512
#define HWN (HH * WW)           // 262144 = 1<<18
#define NB 8
#define NC 16

// Scratch: scatter-winner per target pixel (largest source pixel index wins,
// matching sequential last-write-wins of the reference scatter).
__device__ int   g_winner[NB * HWN];
__device__ float g_M[NB][9];

// ---------------------------------------------------------------------------
// M[b] = (K @ R[b]) @ Kinv  (association A). k-ascending FMA chains.
// DO NOT TOUCH: this exact chain produced rel_err == 0.0.
// ---------------------------------------------------------------------------
__global__ void compute_M_kernel(const float* __restrict__ R,
                                 const float* __restrict__ K,
                                 const float* __restrict__ Kinv) {
    int b = threadIdx.x;
    if (b >= NB) return;
    const float* Rb = R + b * 9;
    float KR[9];
#pragma unroll
    for (int i = 0; i < 3; i++) {
#pragma unroll
        for (int k = 0; k < 3; k++) {
            float s = __fmul_rn(K[i * 3 + 0], Rb[0 * 3 + k]);
            s = __fmaf_rn(K[i * 3 + 1], Rb[1 * 3 + k], s);
            s = __fmaf_rn(K[i * 3 + 2], Rb[2 * 3 + k], s);
            KR[i * 3 + k] = s;
        }
    }
#pragma unroll
    for (int i = 0; i < 3; i++) {
#pragma unroll
        for (int j = 0; j < 3; j++) {
            float s = __fmul_rn(KR[i * 3 + 0], Kinv[0 * 3 + j]);
            s = __fmaf_rn(KR[i * 3 + 1], Kinv[1 * 3 + j], s);
            s = __fmaf_rn(KR[i * 3 + 2], Kinv[2 * 3 + j], s);
            g_M[b][i * 3 + j] = s;
        }
    }
}

// ---------------------------------------------------------------------------
// Winner init: -1 everywhere (vectorized int4 stores)
// ---------------------------------------------------------------------------
__global__ void init_winner_kernel() {
    int i = blockIdx.x * blockDim.x + threadIdx.x;
    ((int4*)g_winner)[i] = make_int4(-1, -1, -1, -1);
}

// ---------------------------------------------------------------------------
// Projection + scatter. DO NOT TOUCH the arithmetic: rel_err == 0.0 with
// frcp_rn-based divide rewrites + gemm FMA x-chain + single-add t.
// ---------------------------------------------------------------------------
__global__ void scatter_kernel(const float* __restrict__ depth,
                               const float* __restrict__ T,
                               const float* __restrict__ K) {
    int idx = blockIdx.x * blockDim.x + threadIdx.x;   // 0 .. NB*HWN-1
    int b = idx >> 18;
    int p = idx & (HWN - 1);
    float gx = (float)(p >> 9);
    float gy = (float)(p & 511);

    float d = fmaxf(depth[idx], 0.1f);

    float rd = __frcp_rn(d);
    float v0 = __fmul_rn(T[b * 3 + 0], rd);
    float v1 = __fmul_rn(T[b * 3 + 1], rd);
    float v2 = __fmul_rn(T[b * 3 + 2], rd);

    const float* M = g_M[b];
    float x0 = __fadd_rn(__fmaf_rn(M[1], gy, __fmul_rn(M[0], gx)), M[2]);
    float x1 = __fadd_rn(__fmaf_rn(M[4], gy, __fmul_rn(M[3], gx)), M[5]);
    float x2 = __fadd_rn(__fmaf_rn(M[7], gy, __fmul_rn(M[6], gx)), M[8]);

    float y0 = __fmaf_rn(K[2], v2, __fmaf_rn(K[1], v1, __fmul_rn(K[0], v0)));
    float y1 = __fmaf_rn(K[5], v2, __fmaf_rn(K[4], v1, __fmul_rn(K[3], v0)));
    float y2 = __fmaf_rn(K[8], v2, __fmaf_rn(K[7], v1, __fmul_rn(K[6], v0)));

    float t0 = __fadd_rn(x0, y0);
    float t1 = __fadd_rn(x1, y1);
    float t2 = __fadd_rn(x2, y2);

    if (t0 == 0.0f) t0 = 1e-4f;
    if (t1 == 0.0f) t1 = 1e-4f;
    if (t2 == 0.0f) t2 = 1e-4f;

    float rt2 = __frcp_rn(t2);
    float u = __fmul_rn(t0, rt2);
    float v = __fmul_rn(t1, rt2);
    u = fminf(fmaxf(u, 0.0f), 511.0f);
    v = fminf(fmaxf(v, 0.0f), 511.0f);

    int q = ((int)u << 9) + (int)v;
    atomicMax(&g_winner[(b << 18) + q], p);
}

// ---------------------------------------------------------------------------
// Gather + maxpool(2x2) + nearest upsample(x2), fused.
// Each block: one pooled tile (4 rows x 64 cols) x 8 channels (half).
// Winners staged in smem; gathers batched 4 channels (16 loads) at a time
// to maximize memory-level parallelism.
// ---------------------------------------------------------------------------
__global__ void __launch_bounds__(256) gather_pool_kernel(
        const float* __restrict__ image, float* __restrict__ out) {
    int blk  = blockIdx.x;
    int half = blk & 1;              // channel half: 0 -> c0..7, 1 -> c8..15
    int tile = (blk >> 1) & 255;     // 256 tiles per image
    int b    = blk >> 9;
    int i0 = (tile >> 2) * 4;        // pooled-row start (0..252)
    int j0 = (tile & 3) * 64;        // pooled-col start (0..192)

    __shared__ int sw[8][128];

    int tid = threadIdx.x;
    const int* wbase = g_winner + (b << 18) + (2 * i0) * WW + 2 * j0;
#pragma unroll
    for (int k = 0; k < 4; k++) {
        int lin = tid + k * 256;          // 0..1023
        int r = lin >> 7, c = lin & 127;
        sw[r][c] = wbase[r * WW + c];
    }
    __syncthreads();

    int li = tid >> 6;                    // 0..3  pooled row within tile
    int jj = tid & 63;                    // 0..63 pooled col within tile
    int w00 = sw[2 * li][2 * jj];
    int w01 = sw[2 * li][2 * jj + 1];
    int w10 = sw[2 * li + 1][2 * jj];
    int w11 = sw[2 * li + 1][2 * jj + 1];

    // clamped addresses (branchless); validity masks applied post-load
    int a00 = max(w00, 0), a01 = max(w01, 0);
    int a10 = max(w10, 0), a11 = max(w11, 0);

    int i2 = i0 + li;
    int j2 = j0 + jj;
    int opix = (2 * i2) * WW + 2 * j2;

    int cbase = half * 8;
#pragma unroll
    for (int cc = 0; cc < 8; cc += 4) {
        float v[16];
#pragma unroll
        for (int c = 0; c < 4; c++) {
            const float* img = image + ((unsigned)((b * NC + cbase + cc + c)) << 18);
            v[c * 4 + 0] = __ldg(img + a00);
            v[c * 4 + 1] = __ldg(img + a01);
            v[c * 4 + 2] = __ldg(img + a10);
            v[c * 4 + 3] = __ldg(img + a11);
        }
#pragma unroll
        for (int c = 0; c < 4; c++) {
            float b0 = (w00 >= 0) ? v[c * 4 + 0] : 0.0f;
            float b1 = (w01 >= 0) ? v[c * 4 + 1] : 0.0f;
            float b2 = (w10 >= 0) ? v[c * 4 + 2] : 0.0f;
            float b3 = (w11 >= 0) ? v[c * 4 + 3] : 0.0f;
            float m = fmaxf(fmaxf(b0, b1), fmaxf(b2, b3));

            float* o = out + ((unsigned)((b * NC + cbase + cc + c)) << 18) + opix;
            float2 vv = make_float2(m, m);
            *(float2*)(o)      = vv;
            *(float2*)(o + WW) = vv;
        }
    }
}

// ---------------------------------------------------------------------------
extern "C" void kernel_launch(void* const* d_in, const int* in_sizes, int n_in,
                              void* d_out, int out_size) {
    const float* image = (const float*)d_in[0];   // [8,16,512,512]
    const float* depth = (const float*)d_in[1];   // [8,512,512]
    const float* T     = (const float*)d_in[2];   // [8,3,1]
    const float* R     = (const float*)d_in[3];   // [8,3,3]
    const float* K     = (const float*)d_in[4];   // [3,3]
    const float* Kinv  = (const float*)d_in[5];   // [3,3]
    float* out = (float*)d_out;

    compute_M_kernel<<<1, 32>>>(R, K, Kinv);
    init_winner_kernel<<<(NB * HWN / 4) / 256, 256>>>();
    scatter_kernel<<<(NB * HWN) / 256, 256>>>(depth, T, K);
    gather_pool_kernel<<<NB * 512, 256>>>(image, out);
}